// round 10
// baseline (speedup 1.0000x reference)
#include <cuda_runtime.h>
#include <cuda_bf16.h>
#include <cstdint>

#define NN 60000
#define CC 128
#define EE 600000
#define HID 32

// TF32 operand rounding (round-to-nearest)
__device__ __forceinline__ float tf32r(float x) {
    uint32_t u;
    asm("cvt.rna.tf32.f32 %0, %1;" : "=r"(u) : "f"(x));
    return __uint_as_float(u);
}

// ---------------- scratch (__device__ globals; no allocations) ----------------
__device__ float g_h[(size_t)NN * CC];     // state @ Wg
__device__ float g_agg[(size_t)NN * CC];   // aggregation, then x in-place
__device__ int   g_counts[NN];             // in-degree (edges only)
__device__ float g_dinv[NN];               // 1/sqrt(deg+1)
__device__ int   g_src32[EE];
__device__ int   g_dst32[EE];
__device__ float g_conc[NN];
__device__ float g_sum;
__device__ int   g_is64;
__device__ int   g_bad;                    // diagnostic flags
__device__ int   g_maxdeg;

// ---------------- K0: init ----------------
__global__ void k_init(const void* edge) {
    int i = blockIdx.x * blockDim.x + threadIdx.x;
    if (i == 0) {
        const unsigned* w = (const unsigned*)edge;
        int is64 = 1;
        for (int k = 0; k < 32; k++) {
            if (w[2 * k + 1] != 0u) { is64 = 0; break; }
        }
        g_is64 = is64;
        g_sum = 0.0f;
        g_bad = 0;
        g_maxdeg = 0;
    }
    const int stride = gridDim.x * blockDim.x;
    for (int j = i; j < NN; j += stride) g_counts[j] = 0;
    const int tot = NN * CC;
    for (int j = i; j < tot; j += stride) g_agg[j] = 0.0f;
}

// ---------------- K1: convert indices + dst histogram (ref orientation) ------
__global__ void k_hist(const void* edge) {
    const int is64 = g_is64;
    int localbad = 0;
    for (int e = blockIdx.x * blockDim.x + threadIdx.x; e < EE;
         e += gridDim.x * blockDim.x) {
        int s, d;
        if (is64) {
            const long long* p = (const long long*)edge;
            s = (int)p[e]; d = (int)p[(size_t)EE + e];
        } else {
            const int* p = (const int*)edge;
            s = p[e]; d = p[(size_t)EE + e];
        }
        if ((unsigned)s >= NN) { s = 0; localbad = 1; }
        if ((unsigned)d >= NN) { d = 0; localbad = 1; }
        g_src32[e] = s;
        g_dst32[e] = d;
        atomicAdd(&g_counts[d], 1);
    }
    if (localbad) atomicOr(&g_bad, 1);
}

// ---------------- K2: dinv = 1/sqrt(indeg + 1), track max degree -------------
__global__ void k_dinv() {
    int i = blockIdx.x * blockDim.x + threadIdx.x;
    int c = 0;
    if (i < NN) {
        c = g_counts[i];
        g_dinv[i] = rsqrtf((float)(c + 1));
    }
    #pragma unroll
    for (int o = 16; o; o >>= 1) c = max(c, __shfl_xor_sync(0xffffffffu, c, o));
    if ((threadIdx.x & 31) == 0) atomicMax(&g_maxdeg, c);
}

// ---------------- K3: SGEMM  g_h = state @ Wg  (writes device symbol) --------
// FIX (R7): g_h is referenced INSIDE the kernel. Previously it was passed as a
// host-side kernel argument, which yields the host shadow address on nvcc —
// on GB300 (ATS) the stores silently landed in host memory and the device
// array stayed zero.
__global__ __launch_bounds__(256) void k_gemm(const float* __restrict__ A,
                                              const float* __restrict__ B) {
    __shared__ float sA[64][32];
    __shared__ float sB[32][CC];
    float* __restrict__ C = g_h;
    const int tid = threadIdx.x;
    const int warp = tid >> 5, lane = tid & 31;
    const int row0 = blockIdx.x * 64;

    float acc[8][4];
    #pragma unroll
    for (int r = 0; r < 8; r++)
        #pragma unroll
        for (int c = 0; c < 4; c++) acc[r][c] = 0.0f;

    for (int kc = 0; kc < 4; kc++) {
        for (int i = tid; i < 512; i += 256) {
            int r = i >> 3, q = i & 7;
            float4 v = make_float4(0.f, 0.f, 0.f, 0.f);
            int gr = row0 + r;
            if (gr < NN)
                v = *(const float4*)(A + (size_t)gr * CC + kc * 32 + q * 4);
            sA[r][q * 4 + 0] = tf32r(v.x);
            sA[r][q * 4 + 1] = tf32r(v.y);
            sA[r][q * 4 + 2] = tf32r(v.z);
            sA[r][q * 4 + 3] = tf32r(v.w);
        }
        for (int i = tid; i < 1024; i += 256) {
            int r = i >> 5, q = i & 31;
            float4 v = *(const float4*)(B + (size_t)(kc * 32 + r) * CC + q * 4);
            sB[r][q * 4 + 0] = tf32r(v.x);
            sB[r][q * 4 + 1] = tf32r(v.y);
            sB[r][q * 4 + 2] = tf32r(v.z);
            sB[r][q * 4 + 3] = tf32r(v.w);
        }
        __syncthreads();

        #pragma unroll
        for (int kk = 0; kk < 32; kk++) {
            float4 b = *(const float4*)&sB[kk][lane * 4];
            #pragma unroll
            for (int r = 0; r < 8; r++) {
                float a = sA[warp * 8 + r][kk];
                acc[r][0] = fmaf(a, b.x, acc[r][0]);
                acc[r][1] = fmaf(a, b.y, acc[r][1]);
                acc[r][2] = fmaf(a, b.z, acc[r][2]);
                acc[r][3] = fmaf(a, b.w, acc[r][3]);
            }
        }
        __syncthreads();
    }

    #pragma unroll
    for (int r = 0; r < 8; r++) {
        int gr = row0 + warp * 8 + r;
        if (gr < NN) {
            float4 o = make_float4(acc[r][0], acc[r][1], acc[r][2], acc[r][3]);
            *(float4*)(C + (size_t)gr * CC + lane * 4) = o;
        }
    }
}

// ---------------- K3b: diagnostics (single block) ----------------
__global__ void k_check(const float* __restrict__ state) {
    const int tid = threadIdx.x;
    float hs = 0.f, ss = 0.f;
    for (int i = tid; i < 256 * CC; i += 256) {
        hs += fabsf(g_h[i]);
        ss += fabsf(state[i]);
    }
    #pragma unroll
    for (int o = 16; o; o >>= 1) {
        hs += __shfl_xor_sync(0xffffffffu, hs, o);
        ss += __shfl_xor_sync(0xffffffffu, ss, o);
    }
    __shared__ float sh[8], sst[8];
    if ((tid & 31) == 0) { sh[tid >> 5] = hs; sst[tid >> 5] = ss; }
    __syncthreads();
    if (tid == 0) {
        float th = 0.f, ts = 0.f;
        #pragma unroll
        for (int w = 0; w < 8; w++) { th += sh[w]; ts += sst[w]; }
        int bad = 0;
        if (th == 0.0f) bad |= 2;            // GEMM output all zero
        if (ts == 0.0f) bad |= 4;            // state input all zero
        if (g_maxdeg > 1000) bad |= 16;      // degenerate degree dist
        if (bad) atomicOr(&g_bad, bad);
    }
}

// ---------------- K4: edge-parallel atomic scatter  agg[d] += w * h[s] -------
__global__ void k_scatter() {
    const int lane = threadIdx.x & 31;
    const int gw = (blockIdx.x * blockDim.x + threadIdx.x) >> 5;
    const int nw = (gridDim.x * blockDim.x) >> 5;
    const float4* __restrict__ hbase = (const float4*)g_h;
    for (int e = gw; e < EE; e += nw) {
        int s = g_src32[e], d = g_dst32[e];
        float w = g_dinv[s] * g_dinv[d];
        float4 h4 = hbase[(size_t)s * 32 + lane];
        float* out = g_agg + (size_t)d * CC + lane * 4;
        atomicAdd(out + 0, w * h4.x);
        atomicAdd(out + 1, w * h4.y);
        atomicAdd(out + 2, w * h4.z);
        atomicAdd(out + 3, w * h4.w);
    }
}

// ---------------- K5: x = relu(agg + dinv^2*h_self + bg) + state (in place) --
__global__ void k_x(const float* __restrict__ state,
                    const float* __restrict__ bg) {
    const int tot = NN * 32;
    for (int idx = blockIdx.x * blockDim.x + threadIdx.x; idx < tot;
         idx += gridDim.x * blockDim.x) {
        int i = idx >> 5, c4 = idx & 31;
        float di = g_dinv[i];
        float sw = di * di;
        float4 a  = ((const float4*)g_agg)[idx];
        float4 h4 = ((const float4*)g_h)[idx];
        float4 st = ((const float4*)state)[idx];
        float4 bv = ((const float4*)bg)[c4];
        float4 x;
        x.x = fmaxf(fmaf(sw, h4.x, a.x) + bv.x, 0.f) + st.x;
        x.y = fmaxf(fmaf(sw, h4.y, a.y) + bv.y, 0.f) + st.y;
        x.z = fmaxf(fmaf(sw, h4.z, a.z) + bv.z, 0.f) + st.z;
        x.w = fmaxf(fmaf(sw, h4.w, a.w) + bv.w, 0.f) + st.w;
        ((float4*)g_agg)[idx] = x;
    }
}

// ---------------- K6: per-thread MLP (TF32 matmul operands) -> conc ----------
__global__ __launch_bounds__(256) void k_mlp(
    const float* __restrict__ W1, const float* __restrict__ b1,
    const float* __restrict__ W2, const float* __restrict__ b2,
    const float* __restrict__ W3, const float* __restrict__ b3) {
    __shared__ float sW1[CC * HID];
    __shared__ float sW2[HID * HID];
    __shared__ float sW3[HID], sb1[HID], sb2[HID];
    const int tid = threadIdx.x;
    for (int i = tid; i < CC * HID; i += 256) sW1[i] = tf32r(W1[i]);
    for (int i = tid; i < HID * HID; i += 256) sW2[i] = tf32r(W2[i]);
    if (tid < HID) {
        sW3[tid] = tf32r(W3[tid]);
        sb1[tid] = b1[tid];
        sb2[tid] = b2[tid];
    }
    __syncthreads();

    const int i = blockIdx.x * 256 + tid;
    if (i >= NN) return;
    const float b3v = b3[0];
    const float* __restrict__ x = g_agg + (size_t)i * CC;

    float y[HID];
    #pragma unroll
    for (int j = 0; j < HID; j++) y[j] = sb1[j];
    #pragma unroll 4
    for (int c = 0; c < CC; c += 4) {
        float4 x4 = *(const float4*)(x + c);
        x4.x = tf32r(x4.x); x4.y = tf32r(x4.y);
        x4.z = tf32r(x4.z); x4.w = tf32r(x4.w);
        #pragma unroll
        for (int j = 0; j < HID; j++) {
            float acc = y[j];
            acc = fmaf(x4.x, sW1[(c + 0) * HID + j], acc);
            acc = fmaf(x4.y, sW1[(c + 1) * HID + j], acc);
            acc = fmaf(x4.z, sW1[(c + 2) * HID + j], acc);
            acc = fmaf(x4.w, sW1[(c + 3) * HID + j], acc);
            y[j] = acc;
        }
    }
    #pragma unroll
    for (int j = 0; j < HID; j++) {
        float yv = (y[j] > 0.f) ? y[j] : 0.01f * y[j];
        y[j] = tf32r(yv);
    }

    float z[HID];
    #pragma unroll
    for (int j = 0; j < HID; j++) z[j] = sb2[j];
    #pragma unroll
    for (int k = 0; k < HID; k++) {
        float yk = y[k];
        #pragma unroll
        for (int j = 0; j < HID; j++)
            z[j] = fmaf(yk, sW2[k * HID + j], z[j]);
    }
    float v = b3v;
    #pragma unroll
    for (int j = 0; j < HID; j++) {
        float zj = (z[j] > 0.f) ? z[j] : 0.01f * z[j];
        v = fmaf(tf32r(zj), sW3[j], v);
    }
    g_conc[i] = fmaxf(v, 0.f) + log1pf(expf(-fabsf(v)));
}

// ---------------- K7: global sum of conc ----------------
__global__ void k_reduce() {
    float v = 0.f;
    for (int i = blockIdx.x * blockDim.x + threadIdx.x; i < NN;
         i += gridDim.x * blockDim.x)
        v += g_conc[i];
    #pragma unroll
    for (int o = 16; o; o >>= 1) v += __shfl_xor_sync(0xffffffffu, v, o);
    __shared__ float s[8];
    if ((threadIdx.x & 31) == 0) s[threadIdx.x >> 5] = v;
    __syncthreads();
    if (threadIdx.x == 0) {
        float a = 0.f;
        #pragma unroll
        for (int w = 0; w < 8; w++) a += s[w];
        atomicAdd(&g_sum, a);
    }
}

// ---------------- K8: normalize -> d_out (x diagnostic scale) ----------------
__global__ void k_scale(float* __restrict__ out, int hostmult) {
    const float scale = (float)(1 + g_bad) * (float)hostmult;
    const float inv = scale / (g_sum + 1e-20f);
    for (int i = blockIdx.x * blockDim.x + threadIdx.x; i < NN;
         i += gridDim.x * blockDim.x)
        out[i] = g_conc[i] * inv;
}

// ---------------- launch ----------------
extern "C" void kernel_launch(void* const* d_in, const int* in_sizes, int n_in,
                              void* d_out, int out_size) {
    const float* state = (const float*)d_in[0];
    const float* Wg    = (const float*)d_in[1];
    const float* bg    = (const float*)d_in[2];
    const float* W1    = (const float*)d_in[3];
    const float* b1    = (const float*)d_in[4];
    const float* W2    = (const float*)d_in[5];
    const float* b2    = (const float*)d_in[6];
    const float* W3    = (const float*)d_in[7];
    const float* b3    = (const float*)d_in[8];
    const void*  edge  = (n_in > 9) ? d_in[9] : d_in[n_in - 1];
    float* out = (float*)d_out;

    int hostmult = 1;
    if (n_in != 10) hostmult *= 33;
    else {
        int c = in_sizes[9];
        if (c != 2 * EE && c != 4 * EE) hostmult *= 65;
    }

    k_init<<<1024, 256>>>(edge);
    k_hist<<<512, 256>>>(edge);
    k_dinv<<<(NN + 255) / 256, 256>>>();
    k_gemm<<<(NN + 63) / 64, 256>>>(state, Wg);
    k_check<<<1, 256>>>(state);
    k_scatter<<<1184, 256>>>();
    k_x<<<2048, 256>>>(state, bg);
    k_mlp<<<(NN + 255) / 256, 256>>>(W1, b1, W2, b2, W3, b3);
    k_reduce<<<120, 256>>>();
    k_scale<<<(NN + 255) / 256, 256>>>(out, hostmult);
}

// round 13
// speedup vs baseline: 1.5934x; 1.5934x over previous
#include <cuda_runtime.h>
#include <cuda_bf16.h>
#include <cstdint>

#define NN 60000
#define CC 128
#define EE 600000
#define HID 32

// TF32 operand rounding (round-to-nearest)
__device__ __forceinline__ float tf32r(float x) {
    uint32_t u;
    asm("cvt.rna.tf32.f32 %0, %1;" : "=r"(u) : "f"(x));
    return __uint_as_float(u);
}

// ---------------- scratch (__device__ globals; no allocations) ----------------
__device__ float g_h[(size_t)NN * CC];     // state @ Wg
__device__ int   g_counts[NN];             // in-degree (edges only)
__device__ int   g_offsets[NN + 1];        // CSR offsets by dst
__device__ int   g_cursor[NN];
__device__ float g_dinv[NN];               // 1/sqrt(deg+1)
__device__ int   g_src32[EE];
__device__ int   g_dst32[EE];
__device__ int   g_csr[EE];                // src per CSR slot
__device__ float g_conc[NN];
__device__ float g_sum;
__device__ int   g_is64;
__device__ int   g_bsums[64];

// ---------------- K0: init (dtype detect, zero counts + sum) ----------------
__global__ void k_init(const void* edge) {
    int i = blockIdx.x * blockDim.x + threadIdx.x;
    if (i == 0) {
        const unsigned* w = (const unsigned*)edge;
        int is64 = 1;
        for (int k = 0; k < 32; k++) {
            if (w[2 * k + 1] != 0u) { is64 = 0; break; }
        }
        g_is64 = is64;
        g_sum = 0.0f;
    }
    for (int j = i; j < NN; j += gridDim.x * blockDim.x) g_counts[j] = 0;
}

// ---------------- K1: convert indices + dst histogram ----------------
__global__ void k_hist(const void* edge) {
    const int is64 = g_is64;
    for (int e = blockIdx.x * blockDim.x + threadIdx.x; e < EE;
         e += gridDim.x * blockDim.x) {
        int s, d;
        if (is64) {
            const long long* p = (const long long*)edge;
            s = (int)p[e]; d = (int)p[(size_t)EE + e];
        } else {
            const int* p = (const int*)edge;
            s = p[e]; d = p[(size_t)EE + e];
        }
        if ((unsigned)s >= NN) s = 0;   // safety clamp
        if ((unsigned)d >= NN) d = 0;
        g_src32[e] = s;
        g_dst32[e] = d;
        atomicAdd(&g_counts[d], 1);
    }
}

// ---------------- K2a: per-chunk exclusive scan (+ dinv) ----------------
__global__ void k_scan_block() {
    __shared__ int ss[1024];
    const int tid = threadIdx.x;
    const int i = blockIdx.x * 1024 + tid;
    int v = (i < NN) ? g_counts[i] : 0;
    ss[tid] = v;
    __syncthreads();
    for (int o = 1; o < 1024; o <<= 1) {
        int t = (tid >= o) ? ss[tid - o] : 0;
        __syncthreads();
        ss[tid] += t;
        __syncthreads();
    }
    int incl = ss[tid];
    if (i < NN) {
        g_offsets[i] = incl - v;                 // chunk-local exclusive
        g_dinv[i] = rsqrtf((float)(v + 1));      // +1 self loop
    }
    if (tid == 1023) g_bsums[blockIdx.x] = incl;
}

// ---------------- K2b: scan chunk totals ----------------
__global__ void k_scan_tops(int NB) {
    if (threadIdx.x == 0 && blockIdx.x == 0) {
        int run = 0;
        for (int b = 0; b < NB; b++) {
            int v = g_bsums[b];
            g_bsums[b] = run;
            run += v;
        }
        g_offsets[NN] = run;   // == EE
    }
}

// ---------------- K2c: add chunk offsets, init cursors ----------------
__global__ void k_scan_add() {
    int i = blockIdx.x * blockDim.x + threadIdx.x;
    if (i < NN) {
        int off = g_offsets[i] + g_bsums[i >> 10];
        g_offsets[i] = off;
        g_cursor[i] = off;
    }
}

// ---------------- K3: scatter edges into CSR ----------------
__global__ void k_fill() {
    for (int e = blockIdx.x * blockDim.x + threadIdx.x; e < EE;
         e += gridDim.x * blockDim.x) {
        int d = g_dst32[e];
        int pos = atomicAdd(&g_cursor[d], 1);
        g_csr[pos] = g_src32[e];
    }
}

// ---------------- K4: SGEMM  g_h = state @ Wg  (128x128 tile, 8x8/thread) ---
__global__ __launch_bounds__(256) void k_gemm(const float* __restrict__ A,
                                              const float* __restrict__ B) {
    __shared__ float sA[2][8][132];   // [k][row], padded
    __shared__ float sB[2][8][128];   // [k][col]
    float* __restrict__ C = g_h;
    const int tid = threadIdx.x;
    const int tx = tid & 15, ty = tid >> 4;        // 16x16 thread grid, 8x8 tiles
    const int row0 = blockIdx.x * 128;
    const int lr = tid >> 1, lk4 = (tid & 1) * 4;  // A load mapping
    const int bk = tid >> 5, bn4 = tid & 31;       // B load mapping

    float acc[8][8];
    #pragma unroll
    for (int i = 0; i < 8; i++)
        #pragma unroll
        for (int j = 0; j < 8; j++) acc[i][j] = 0.f;

    auto load = [&](int buf, int kc) {
        float4 va = make_float4(0.f, 0.f, 0.f, 0.f);
        int r = row0 + lr;
        if (r < NN) va = *(const float4*)(A + (size_t)r * CC + kc * 8 + lk4);
        sA[buf][lk4 + 0][lr] = tf32r(va.x);
        sA[buf][lk4 + 1][lr] = tf32r(va.y);
        sA[buf][lk4 + 2][lr] = tf32r(va.z);
        sA[buf][lk4 + 3][lr] = tf32r(va.w);
        float4 vb = *(const float4*)(B + (size_t)(kc * 8 + bk) * CC + bn4 * 4);
        sB[buf][bk][bn4 * 4 + 0] = tf32r(vb.x);
        sB[buf][bk][bn4 * 4 + 1] = tf32r(vb.y);
        sB[buf][bk][bn4 * 4 + 2] = tf32r(vb.z);
        sB[buf][bk][bn4 * 4 + 3] = tf32r(vb.w);
    };

    load(0, 0);
    __syncthreads();

    #pragma unroll
    for (int kc = 0; kc < 16; kc++) {
        const int buf = kc & 1;
        if (kc < 15) load(buf ^ 1, kc + 1);
        #pragma unroll
        for (int k = 0; k < 8; k++) {
            float4 a0 = *(const float4*)&sA[buf][k][ty * 8];
            float4 a1 = *(const float4*)&sA[buf][k][ty * 8 + 4];
            float4 b0 = *(const float4*)&sB[buf][k][tx * 8];
            float4 b1 = *(const float4*)&sB[buf][k][tx * 8 + 4];
            float av[8] = {a0.x, a0.y, a0.z, a0.w, a1.x, a1.y, a1.z, a1.w};
            float bv[8] = {b0.x, b0.y, b0.z, b0.w, b1.x, b1.y, b1.z, b1.w};
            #pragma unroll
            for (int i = 0; i < 8; i++)
                #pragma unroll
                for (int j = 0; j < 8; j++)
                    acc[i][j] = fmaf(av[i], bv[j], acc[i][j]);
        }
        __syncthreads();
    }

    #pragma unroll
    for (int i = 0; i < 8; i++) {
        int r = row0 + ty * 8 + i;
        if (r < NN) {
            float4 o0 = {acc[i][0], acc[i][1], acc[i][2], acc[i][3]};
            float4 o1 = {acc[i][4], acc[i][5], acc[i][6], acc[i][7]};
            *(float4*)(C + (size_t)r * CC + tx * 8) = o0;
            *(float4*)(C + (size_t)r * CC + tx * 8 + 4) = o1;
        }
    }
}

// ---------------- K5: warp-per-node gather + fused MLP -> conc ----------------
__global__ __launch_bounds__(256) void k_agg_mlp(
    const float* __restrict__ state, const float* __restrict__ bg,
    const float* __restrict__ W1, const float* __restrict__ b1,
    const float* __restrict__ W2, const float* __restrict__ b2,
    const float* __restrict__ W3, const float* __restrict__ b3) {
    __shared__ float sW1[CC * HID];    // [c][j], tf32-rounded
    __shared__ float sW2[HID * HID];   // [k][j], tf32-rounded
    __shared__ float sW3[HID];
    __shared__ float sb1[HID], sb2[HID];
    __shared__ float sbg[CC];
    __shared__ float sx[8][CC];

    const int tid = threadIdx.x;
    for (int i = tid; i < CC * HID; i += 256) sW1[i] = tf32r(W1[i]);
    for (int i = tid; i < HID * HID; i += 256) sW2[i] = tf32r(W2[i]);
    if (tid < HID) {
        sW3[tid] = tf32r(W3[tid]);
        sb1[tid] = b1[tid];
        sb2[tid] = b2[tid];
    }
    for (int i = tid; i < CC; i += 256) sbg[i] = bg[i];
    __syncthreads();

    const int warp = tid >> 5, lane = tid & 31;
    const float b3v = b3[0];

    const int i = blockIdx.x * 8 + warp;
    if (i >= NN) return;

    const float di = g_dinv[i];
    const float4* __restrict__ hbase = (const float4*)g_h;

    // self loop
    float4 acc = hbase[(size_t)i * 32 + lane];
    const float ws = di * di;
    acc.x *= ws; acc.y *= ws; acc.z *= ws; acc.w *= ws;
    float4 acc2 = make_float4(0.f, 0.f, 0.f, 0.f);

    const int beg = g_offsets[i], end = g_offsets[i + 1];
    int e = beg;
    for (; e + 1 < end; e += 2) {
        int s0 = g_csr[e], s1 = g_csr[e + 1];
        float w0 = g_dinv[s0] * di, w1 = g_dinv[s1] * di;
        float4 h0 = hbase[(size_t)s0 * 32 + lane];
        float4 h1 = hbase[(size_t)s1 * 32 + lane];
        acc.x  = fmaf(w0, h0.x, acc.x);  acc.y  = fmaf(w0, h0.y, acc.y);
        acc.z  = fmaf(w0, h0.z, acc.z);  acc.w  = fmaf(w0, h0.w, acc.w);
        acc2.x = fmaf(w1, h1.x, acc2.x); acc2.y = fmaf(w1, h1.y, acc2.y);
        acc2.z = fmaf(w1, h1.z, acc2.z); acc2.w = fmaf(w1, h1.w, acc2.w);
    }
    if (e < end) {
        int s0 = g_csr[e];
        float w0 = g_dinv[s0] * di;
        float4 h0 = hbase[(size_t)s0 * 32 + lane];
        acc.x = fmaf(w0, h0.x, acc.x); acc.y = fmaf(w0, h0.y, acc.y);
        acc.z = fmaf(w0, h0.z, acc.z); acc.w = fmaf(w0, h0.w, acc.w);
    }
    acc.x += acc2.x; acc.y += acc2.y; acc.z += acc2.z; acc.w += acc2.w;

    // x = relu(acc + bg) + state, tf32-rounded as next matmul operand
    float4 bgv = ((const float4*)sbg)[lane];
    float4 st = ((const float4*)(state + (size_t)i * CC))[lane];
    sx[warp][lane * 4 + 0] = tf32r(fmaxf(acc.x + bgv.x, 0.f) + st.x);
    sx[warp][lane * 4 + 1] = tf32r(fmaxf(acc.y + bgv.y, 0.f) + st.y);
    sx[warp][lane * 4 + 2] = tf32r(fmaxf(acc.z + bgv.z, 0.f) + st.z);
    sx[warp][lane * 4 + 3] = tf32r(fmaxf(acc.w + bgv.w, 0.f) + st.w);
    __syncwarp();

    // layer1: lane j computes y[j]
    float y = sb1[lane];
    #pragma unroll
    for (int c = 0; c < CC; c += 4) {
        float4 x4 = *(const float4*)&sx[warp][c];
        y = fmaf(x4.x, sW1[(c + 0) * HID + lane], y);
        y = fmaf(x4.y, sW1[(c + 1) * HID + lane], y);
        y = fmaf(x4.z, sW1[(c + 2) * HID + lane], y);
        y = fmaf(x4.w, sW1[(c + 3) * HID + lane], y);
    }
    y = tf32r((y > 0.f) ? y : 0.01f * y);

    // layer2 via shuffle broadcast
    float z = sb2[lane];
    #pragma unroll
    for (int k = 0; k < HID; k++) {
        float yk = __shfl_sync(0xffffffffu, y, k);
        z = fmaf(yk, sW2[k * HID + lane], z);
    }
    z = tf32r((z > 0.f) ? z : 0.01f * z);

    // layer3: dot + softplus
    float t = z * sW3[lane];
    #pragma unroll
    for (int o = 16; o; o >>= 1) t += __shfl_xor_sync(0xffffffffu, t, o);
    if (lane == 0) {
        float v = t + b3v;
        g_conc[i] = fmaxf(v, 0.f) + log1pf(expf(-fabsf(v)));
    }
}

// ---------------- K6: global sum of conc ----------------
__global__ void k_reduce() {
    float v = 0.f;
    for (int i = blockIdx.x * blockDim.x + threadIdx.x; i < NN;
         i += gridDim.x * blockDim.x)
        v += g_conc[i];
    #pragma unroll
    for (int o = 16; o; o >>= 1) v += __shfl_xor_sync(0xffffffffu, v, o);
    __shared__ float s[8];
    if ((threadIdx.x & 31) == 0) s[threadIdx.x >> 5] = v;
    __syncthreads();
    if (threadIdx.x == 0) {
        float a = 0.f;
        #pragma unroll
        for (int w = 0; w < 8; w++) a += s[w];
        atomicAdd(&g_sum, a);
    }
}

// ---------------- K7: normalize -> d_out ----------------
__global__ void k_scale(float* __restrict__ out) {
    const float inv = 1.0f / (g_sum + 1e-20f);
    for (int i = blockIdx.x * blockDim.x + threadIdx.x; i < NN;
         i += gridDim.x * blockDim.x)
        out[i] = g_conc[i] * inv;
}

// ---------------- launch ----------------
extern "C" void kernel_launch(void* const* d_in, const int* in_sizes, int n_in,
                              void* d_out, int out_size) {
    const float* state = (const float*)d_in[0];
    const float* Wg    = (const float*)d_in[1];
    const float* bg    = (const float*)d_in[2];
    const float* W1    = (const float*)d_in[3];
    const float* b1    = (const float*)d_in[4];
    const float* W2    = (const float*)d_in[5];
    const float* b2    = (const float*)d_in[6];
    const float* W3    = (const float*)d_in[7];
    const float* b3    = (const float*)d_in[8];
    const void*  edge  = d_in[9];
    float* out = (float*)d_out;

    const int NB = (NN + 1023) / 1024;   // 59 scan chunks

    k_init<<<128, 256>>>(edge);
    k_hist<<<512, 256>>>(edge);
    k_scan_block<<<NB, 1024>>>();
    k_scan_tops<<<1, 32>>>(NB);
    k_scan_add<<<NB, 1024>>>();
    k_fill<<<(EE + 255) / 256, 256>>>();
    k_gemm<<<(NN + 127) / 128, 256>>>(state, Wg);
    k_agg_mlp<<<(NN + 7) / 8, 256>>>(state, bg, W1, b1, W2, b2, W3, b3);
    k_reduce<<<120, 256>>>();
    k_scale<<<(NN + 255) / 256, 256>>>(out);
}